// round 4
// baseline (speedup 1.0000x reference)
#include <cuda_runtime.h>

typedef unsigned long long ull;

#define NQ 12
#define NS 4096
#define TPB 256
#define NL 3

// Packed per-(layer,wire) gates: 12 b64 per gate:
// [x00,y00,-y00, x01,y01,-y01, x10,y10,-y10, x11,y11,-y11], each lane-duplicated.
__device__ ull g_gates_pk[NL * NQ * 12];

__device__ __forceinline__ ull pk(float a, float b) {
    ull r; asm("mov.b64 %0, {%1,%2};" : "=l"(r) : "f"(a), "f"(b)); return r;
}
__device__ __forceinline__ void unpk(ull v, float& a, float& b) {
    asm("mov.b64 {%0,%1}, %2;" : "=f"(a), "=f"(b) : "l"(v));
}
#define FMA2(d, a, b, c) asm("fma.rn.f32x2 %0, %1, %2, %3;" : "=l"(d) : "l"(a), "l"(b), "l"(c))
#define MUL2(d, a, b)    asm("mul.rn.f32x2 %0, %1, %2;"     : "=l"(d) : "l"(a), "l"(b))

__global__ void prep_gates(const float* __restrict__ params) {
    int t = blockIdx.x * blockDim.x + threadIdx.x;
    if (t >= NL * NQ) return;
    float t0 = params[t * 3 + 0], t1 = params[t * 3 + 1], t2 = params[t * 3 + 2];
    float c0 = cosf(0.5f * t0), s0 = sinf(0.5f * t0);
    float cp = cosf(0.5f * t1), sp = sinf(0.5f * t1);
    float c2 = cosf(0.5f * t2), s2 = sinf(0.5f * t2);
    float A_re = cp * c0, A_im = -sp * c0;
    float B_re = -cp * s0, B_im = sp * s0;
    float C_re = cp * s0, C_im = sp * s0;
    float D_re = cp * c0, D_im = sp * c0;
    float gx[4], gy[4];
    gx[0] = c2 * A_re - s2 * C_re;  gy[0] = c2 * A_im - s2 * C_im;  // g00
    gx[1] = c2 * B_re - s2 * D_re;  gy[1] = c2 * B_im - s2 * D_im;  // g01
    gx[2] = s2 * A_re + c2 * C_re;  gy[2] = s2 * A_im + c2 * C_im;  // g10
    gx[3] = s2 * B_re + c2 * D_re;  gy[3] = s2 * B_im + c2 * D_im;  // g11
    ull* g = &g_gates_pk[t * 12];
    #pragma unroll
    for (int e = 0; e < 4; e++) {
        g[e * 3 + 0] = pk(gx[e], gx[e]);
        g[e * 3 + 1] = pk(gy[e], gy[e]);
        g[e * 3 + 2] = pk(-gy[e], -gy[e]);
    }
}

struct Gp { ull x00, y00, n00, x01, y01, n01, x10, y10, n10, x11, y11, n11; };

__device__ __forceinline__ Gp load_gate(const ull* gsm, int l, int w) {
    const ull* g = &gsm[(l * NQ + w) * 12];
    Gp r;
    r.x00 = g[0];  r.y00 = g[1];  r.n00 = g[2];
    r.x01 = g[3];  r.y01 = g[4];  r.n01 = g[5];
    r.x10 = g[6];  r.y10 = g[7];  r.n10 = g[8];
    r.x11 = g[9];  r.y11 = g[10]; r.n11 = g[11];
    return r;
}

// complex 2x2 gate on two amplitudes, both lanes = independent samples
__device__ __forceinline__ void apply2(const Gp& g, ull& are, ull& aim, ull& bre, ull& bim) {
    ull nare, naim, nbre, nbim;
    MUL2(nare, g.x00, are); FMA2(nare, g.n00, aim, nare); FMA2(nare, g.x01, bre, nare); FMA2(nare, g.n01, bim, nare);
    MUL2(naim, g.y00, are); FMA2(naim, g.x00, aim, naim); FMA2(naim, g.y01, bre, naim); FMA2(naim, g.x01, bim, naim);
    MUL2(nbre, g.x10, are); FMA2(nbre, g.n10, aim, nbre); FMA2(nbre, g.x11, bre, nbre); FMA2(nbre, g.n11, bim, nbre);
    MUL2(nbim, g.y10, are); FMA2(nbim, g.x10, aim, nbim); FMA2(nbim, g.y11, bre, nbim); FMA2(nbim, g.x11, bim, nbim);
    are = nare; aim = naim; bre = nbre; bim = nbim;
}

__device__ __forceinline__ void gate_on_bit(const Gp& g, ull re[16], ull im[16], int k) {
    #pragma unroll
    for (int l = 0; l < 16; l++)
        if (!(l & (1 << k)))
            apply2(g, re[l], im[l], re[l | (1 << k)], im[l | (1 << k)]);
}

__device__ __forceinline__ void cnot_loc(ull re[16], ull im[16], int c, int tg) {
    #pragma unroll
    for (int l = 0; l < 16; l++)
        if ((l & (1 << c)) && !(l & (1 << tg))) {
            ull t;
            t = re[l]; re[l] = re[l | (1 << tg)]; re[l | (1 << tg)] = t;
            t = im[l]; im[l] = im[l | (1 << tg)]; im[l | (1 << tg)] = t;
        }
}

// Stage maps (identical to verified R3 version)
__device__ __forceinline__ int gS0(int t, int l) { return (l << 8) | t; }
__device__ __forceinline__ int gS1(int t, int l) { return ((t >> 5) << 9) | (l << 5) | (t & 31); }
__device__ __forceinline__ int gS2(int t, int l) { return ((t >> 5) << 9) | (((t >> 2) & 7) << 6) | (l << 2) | (t & 3); }
__device__ __forceinline__ int gS3(int t, int l) { return ((t >> 5) << 9) | ((t & 31) << 4) | l; }
__device__ __forceinline__ int swz(int g, int m) { return g ^ ((g >> 4) & m); }

#define SMEM_BYTES ((2 * NS + NL * NQ * 12 + 24) * 8 + 64)

__global__ __launch_bounds__(TPB, 2) void qsim(
    const float* __restrict__ x, const float* __restrict__ head_w,
    const float* __restrict__ head_b, float* __restrict__ out) {
    extern __shared__ ull sh[];
    ull* st_re = sh;                    // 4096
    ull* st_im = sh + NS;               // 4096
    ull* gsm   = sh + 2 * NS;           // 432
    ull* cscp  = gsm + NL * NQ * 12;    // 12
    ull* cssp  = cscp + NQ;             // 12
    float* wred = (float*)(cssp + NQ);  // 16 floats

    int b = blockIdx.x, t = threadIdx.x;
    int s0 = 2 * b, s1 = 2 * b + 1;

    for (int i = t; i < NL * NQ * 12; i += TPB) gsm[i] = g_gates_pk[i];
    if (t < NQ) {
        float xA = x[s0 * NQ + t], xB = x[s1 * NQ + t];
        cscp[t] = pk(cosf(0.5f * xA), cosf(0.5f * xB));
        cssp[t] = pk(sinf(0.5f * xA), sinf(0.5f * xB));
    }
    __syncthreads();

    ull rre[16], rim[16];

    // --- Init: product state in S0 layout (t = wires 4..11, l = wires 0..3) ---
    {
        ull rB = ((t >> 7) & 1) ? cssp[4] : cscp[4];
        #pragma unroll
        for (int w = 5; w < NQ; w++) {
            ull f = ((t >> (11 - w)) & 1) ? cssp[w] : cscp[w];
            MUL2(rB, rB, f);
        }
        int kB = __popc(t & 0xFF);
        #pragma unroll
        for (int l = 0; l < 16; l++) {
            ull v = ((l >> 3) & 1) ? cssp[0] : cscp[0];
            #pragma unroll
            for (int w = 1; w < 4; w++) {
                ull f = ((l >> (3 - w)) & 1) ? cssp[w] : cscp[w];
                MUL2(v, v, f);
            }
            MUL2(v, v, rB);
            ull vn = v ^ 0x8000000080000000ULL;
            int m = (kB + __popc(l)) & 3;       // (-i)^m
            rre[l] = (m == 0) ? v : ((m == 2) ? vn : 0ULL);
            rim[l] = (m == 1) ? vn : ((m == 3) ? v : 0ULL);
        }
    }

    #define XPOSE(GSRC, GDST, MASK) do {                               \
        __syncthreads();                                               \
        _Pragma("unroll")                                              \
        for (int i_ = 0; i_ < 16; i_++) {                              \
            int a_ = swz(GSRC(t, i_), MASK);                           \
            st_re[a_] = rre[i_]; st_im[a_] = rim[i_];                  \
        }                                                              \
        __syncthreads();                                               \
        _Pragma("unroll")                                              \
        for (int i_ = 0; i_ < 16; i_++) {                              \
            int a_ = swz(GDST(t, i_), MASK);                           \
            rre[i_] = st_re[a_]; rim[i_] = st_im[a_];                  \
        }                                                              \
    } while (0)

    for (int l = 0; l < NL; l++) {
        // S0: wires 0-3 on local bits 3..0
        {
            Gp G0 = load_gate(gsm, l, 0);  gate_on_bit(G0, rre, rim, 3);
            Gp G1 = load_gate(gsm, l, 1);  gate_on_bit(G1, rre, rim, 2);
            Gp G2_ = load_gate(gsm, l, 2); gate_on_bit(G2_, rre, rim, 1);
            Gp G3 = load_gate(gsm, l, 3);  gate_on_bit(G3, rre, rim, 0);
            cnot_loc(rre, rim, 3, 2); cnot_loc(rre, rim, 2, 1); cnot_loc(rre, rim, 1, 0);
        }
        XPOSE(gS0, gS1, 0);
        // S1: wires 3(l3),4(l2),5(l1),6(l0); gates on 4,5,6
        {
            Gp G4 = load_gate(gsm, l, 4); gate_on_bit(G4, rre, rim, 2);
            Gp G5 = load_gate(gsm, l, 5); gate_on_bit(G5, rre, rim, 1);
            Gp G6 = load_gate(gsm, l, 6); gate_on_bit(G6, rre, rim, 0);
            cnot_loc(rre, rim, 3, 2); cnot_loc(rre, rim, 2, 1); cnot_loc(rre, rim, 1, 0);
        }
        XPOSE(gS1, gS2, 0xC);
        // S2: wires 6(l3),7(l2),8(l1),9(l0); gates on 7,8,9
        {
            Gp G7 = load_gate(gsm, l, 7); gate_on_bit(G7, rre, rim, 2);
            Gp G8 = load_gate(gsm, l, 8); gate_on_bit(G8, rre, rim, 1);
            Gp G9 = load_gate(gsm, l, 9); gate_on_bit(G9, rre, rim, 0);
            cnot_loc(rre, rim, 3, 2); cnot_loc(rre, rim, 2, 1); cnot_loc(rre, rim, 1, 0);
        }
        XPOSE(gS2, gS3, 0xF);
        // S3: wires 8(l3),9(l2),10(l1),11(l0); gates on 10,11
        {
            Gp Ga = load_gate(gsm, l, 10); gate_on_bit(Ga, rre, rim, 1);
            Gp Gb = load_gate(gsm, l, 11); gate_on_bit(Gb, rre, rim, 0);
            cnot_loc(rre, rim, 2, 1); cnot_loc(rre, rim, 1, 0);
        }
        if (l < NL - 1) XPOSE(gS3, gS0, 0xF);
    }

    // --- Readout from S3 registers ---
    float hw[NQ];
    #pragma unroll
    for (int w = 0; w < NQ; w++) hw[w] = head_w[w];
    float swt = 0.f;
    {
        int g = gS3(t, 0);
        #pragma unroll
        for (int w = 0; w < 8; w++)
            swt += ((g >> (11 - w)) & 1) ? -hw[w] : hw[w];
    }
    float accA = 0.f, accB = 0.f;
    #pragma unroll
    for (int l = 0; l < 16; l++) {
        ull p;
        MUL2(p, rre[l], rre[l]);
        FMA2(p, rim[l], rim[l], p);
        float pA, pB; unpk(p, pA, pB);
        float swl = 0.f;
        #pragma unroll
        for (int w = 8; w < 12; w++)
            swl += ((l >> (11 - w)) & 1) ? -hw[w] : hw[w];
        float sw = swt + swl;
        accA = fmaf(pA, sw, accA);
        accB = fmaf(pB, sw, accB);
    }
    #pragma unroll
    for (int o = 16; o > 0; o >>= 1) {
        accA += __shfl_xor_sync(0xFFFFFFFFu, accA, o);
        accB += __shfl_xor_sync(0xFFFFFFFFu, accB, o);
    }
    if ((t & 31) == 0) {
        wred[(t >> 5) * 2]     = accA;
        wred[(t >> 5) * 2 + 1] = accB;
    }
    __syncthreads();
    if (t == 0) {
        float tA = 0.f, tB = 0.f;
        #pragma unroll
        for (int i = 0; i < TPB / 32; i++) { tA += wred[i * 2]; tB += wred[i * 2 + 1]; }
        float bb = head_b[0];
        out[s0] = tA + bb;
        out[s1] = tB + bb;
    }
}

extern "C" void kernel_launch(void* const* d_in, const int* in_sizes, int n_in,
                              void* d_out, int out_size) {
    const float* x      = (const float*)d_in[0];
    const float* params = (const float*)d_in[1];
    const float* head_w = (const float*)d_in[2];
    const float* head_b = (const float*)d_in[3];
    float* out = (float*)d_out;
    int B = in_sizes[0] / NQ;
    static int smem_set = 0;
    if (!smem_set) {
        cudaFuncSetAttribute(qsim, cudaFuncAttributeMaxDynamicSharedMemorySize, SMEM_BYTES);
        smem_set = 1;
    }
    prep_gates<<<1, 64>>>(params);
    qsim<<<B / 2, TPB, SMEM_BYTES>>>(x, head_w, head_b, out);
}

// round 5
// speedup vs baseline: 1.0384x; 1.0384x over previous
#include <cuda_runtime.h>

#define NQ 12
#define NS 4096
#define TPB 256
#define NL 3

__device__ float g_gates[NL * NQ * 8];

__global__ void prep_gates(const float* __restrict__ params) {
    int t = blockIdx.x * blockDim.x + threadIdx.x;
    if (t >= NL * NQ) return;
    float t0 = params[t * 3 + 0], t1 = params[t * 3 + 1], t2 = params[t * 3 + 2];
    float c0 = cosf(0.5f * t0), s0 = sinf(0.5f * t0);
    float cp = cosf(0.5f * t1), sp = sinf(0.5f * t1);
    float c2 = cosf(0.5f * t2), s2 = sinf(0.5f * t2);
    float A_re = cp * c0, A_im = -sp * c0;
    float B_re = -cp * s0, B_im = sp * s0;
    float C_re = cp * s0, C_im = sp * s0;
    float D_re = cp * c0, D_im = sp * c0;
    float* g = &g_gates[t * 8];
    g[0] = c2 * A_re - s2 * C_re;  g[1] = c2 * A_im - s2 * C_im;
    g[2] = c2 * B_re - s2 * D_re;  g[3] = c2 * B_im - s2 * D_im;
    g[4] = s2 * A_re + c2 * C_re;  g[5] = s2 * A_im + c2 * C_im;
    g[6] = s2 * B_re + c2 * D_re;  g[7] = s2 * B_im + c2 * D_im;
}

struct G2 { float2 g00, g01, g10, g11; };

__device__ __forceinline__ void apply_pair(const G2& g, float2& a, float2& b) {
    float2 na, nb;
    na.x = g.g00.x * a.x - g.g00.y * a.y + g.g01.x * b.x - g.g01.y * b.y;
    na.y = g.g00.x * a.y + g.g00.y * a.x + g.g01.x * b.y + g.g01.y * b.x;
    nb.x = g.g10.x * a.x - g.g10.y * a.y + g.g11.x * b.x - g.g11.y * b.y;
    nb.y = g.g10.x * a.y + g.g10.y * a.x + g.g11.x * b.y + g.g11.y * b.x;
    a = na; b = nb;
}

__device__ __forceinline__ G2 load_gate(const float* gsm, int l, int w) {
    const float* g = &gsm[(l * NQ + w) * 8];
    G2 r;
    r.g00 = make_float2(g[0], g[1]);
    r.g01 = make_float2(g[2], g[3]);
    r.g10 = make_float2(g[4], g[5]);
    r.g11 = make_float2(g[6], g[7]);
    return r;
}

__device__ __forceinline__ void gate_on_bit(const G2& g, float2 r[16], int k) {
    #pragma unroll
    for (int l = 0; l < 16; l++)
        if (!(l & (1 << k))) apply_pair(g, r[l], r[l | (1 << k)]);
}

__device__ __forceinline__ void cnot_loc(float2 r[16], int c, int tg) {
    #pragma unroll
    for (int l = 0; l < 16; l++)
        if ((l & (1 << c)) && !(l & (1 << tg))) {
            float2 tmp = r[l]; r[l] = r[l | (1 << tg)]; r[l | (1 << tg)] = tmp;
        }
}

// Stage maps (verified R3). t = thread (8 bits), l = local (4 bits).
__device__ __forceinline__ int gS0(int t, int l) { return (l << 8) | t; }
__device__ __forceinline__ int gS1(int t, int l) { return ((t >> 5) << 9) | (l << 5) | (t & 31); }
__device__ __forceinline__ int gS2(int t, int l) { return ((t >> 5) << 9) | (((t >> 2) & 7) << 6) | (l << 2) | (t & 3); }
__device__ __forceinline__ int gS3(int t, int l) { return ((t >> 5) << 9) | ((t & 31) << 4) | l; }
__device__ __forceinline__ int swz(int g, int m) { return g ^ ((g >> 4) & m); }

__global__ __launch_bounds__(TPB, 3) void qsim(
    const float* __restrict__ x, const float* __restrict__ head_w,
    const float* __restrict__ head_b, float* __restrict__ out) {
    __shared__ float2 st[NS];          // 32 KB transpose buffer
    __shared__ float gsm[NL * NQ * 8];
    __shared__ float csC[NQ], csS[NQ];
    __shared__ float wred[TPB / 32];

    int b = blockIdx.x, t = threadIdx.x;

    for (int i = t; i < NL * NQ * 8; i += TPB) gsm[i] = g_gates[i];
    if (t < NQ) {
        float xv = x[b * NQ + t];
        csC[t] = cosf(0.5f * xv);
        csS[t] = sinf(0.5f * xv);
    }
    __syncthreads();

    float2 r[16];

    // --- Init: product state in S0 layout (t = wires 4..11, l = wires 0..3) ---
    {
        float rB = 1.f;
        #pragma unroll
        for (int w = 4; w < NQ; w++) {
            int bit = (t >> (11 - w)) & 1;
            rB *= bit ? csS[w] : csC[w];
        }
        int kB = __popc(t & 0xFF);
        #pragma unroll
        for (int l = 0; l < 16; l++) {
            float rA = 1.f;
            #pragma unroll
            for (int w = 0; w < 4; w++) {
                int bit = (l >> (3 - w)) & 1;
                rA *= bit ? csS[w] : csC[w];
            }
            float v = rA * rB;
            int m = (kB + __popc(l)) & 3;   // (-i)^m
            float2 a;
            a.x = (m == 0) ? v : ((m == 2) ? -v : 0.f);
            a.y = (m == 1) ? -v : ((m == 3) ? v : 0.f);
            r[l] = a;
        }
    }

    #define XPOSE(GSRC, GDST, MASK) do {                              \
        __syncthreads();                                              \
        _Pragma("unroll")                                             \
        for (int i_ = 0; i_ < 16; i_++) st[swz(GSRC(t, i_), MASK)] = r[i_]; \
        __syncthreads();                                              \
        _Pragma("unroll")                                             \
        for (int i_ = 0; i_ < 16; i_++) r[i_] = st[swz(GDST(t, i_), MASK)]; \
    } while (0)

    for (int l = 0; l < NL; l++) {
        // S0: wires 0-3 on local bits 3..0
        {
            G2 G0 = load_gate(gsm, l, 0);  gate_on_bit(G0, r, 3);
            G2 G1 = load_gate(gsm, l, 1);  gate_on_bit(G1, r, 2);
            G2 G2_ = load_gate(gsm, l, 2); gate_on_bit(G2_, r, 1);
            G2 G3 = load_gate(gsm, l, 3);  gate_on_bit(G3, r, 0);
            cnot_loc(r, 3, 2); cnot_loc(r, 2, 1); cnot_loc(r, 1, 0);
        }
        XPOSE(gS0, gS1, 0);
        // S1: wires 3(l3),4(l2),5(l1),6(l0); gates on 4,5,6
        {
            G2 G4 = load_gate(gsm, l, 4); gate_on_bit(G4, r, 2);
            G2 G5 = load_gate(gsm, l, 5); gate_on_bit(G5, r, 1);
            G2 G6 = load_gate(gsm, l, 6); gate_on_bit(G6, r, 0);
            cnot_loc(r, 3, 2); cnot_loc(r, 2, 1); cnot_loc(r, 1, 0);
        }
        XPOSE(gS1, gS2, 0xC);
        // S2: wires 6(l3),7(l2),8(l1),9(l0); gates on 7,8,9
        {
            G2 G7 = load_gate(gsm, l, 7); gate_on_bit(G7, r, 2);
            G2 G8 = load_gate(gsm, l, 8); gate_on_bit(G8, r, 1);
            G2 G9 = load_gate(gsm, l, 9); gate_on_bit(G9, r, 0);
            cnot_loc(r, 3, 2); cnot_loc(r, 2, 1); cnot_loc(r, 1, 0);
        }
        XPOSE(gS2, gS3, 0xF);
        // S3: wires 8(l3),9(l2),10(l1),11(l0); gates on 10,11
        {
            G2 Ga = load_gate(gsm, l, 10); gate_on_bit(Ga, r, 1);
            G2 Gb = load_gate(gsm, l, 11); gate_on_bit(Gb, r, 0);
            cnot_loc(r, 2, 1); cnot_loc(r, 1, 0);
        }
        if (l < NL - 1) XPOSE(gS3, gS0, 0xF);
    }

    // --- Readout from S3 registers ---
    // thread part: wires 0..7 live in g bits 11..4
    float swt = 0.f;
    {
        int g = gS3(t, 0);
        #pragma unroll
        for (int w = 0; w < 8; w++)
            swt += ((g >> (11 - w)) & 1) ? -head_w[w] : head_w[w];
    }
    float acc = 0.f;
    #pragma unroll
    for (int l = 0; l < 16; l++) {
        float2 a = r[l];
        float p = a.x * a.x + a.y * a.y;
        float swl = 0.f;
        #pragma unroll
        for (int w = 8; w < 12; w++)
            swl += ((l >> (11 - w)) & 1) ? -head_w[w] : head_w[w];
        acc = fmaf(p, swt + swl, acc);
    }
    #pragma unroll
    for (int o = 16; o > 0; o >>= 1) acc += __shfl_xor_sync(0xFFFFFFFFu, acc, o);
    if ((t & 31) == 0) wred[t >> 5] = acc;
    __syncthreads();
    if (t == 0) {
        float tot = 0.f;
        #pragma unroll
        for (int i = 0; i < TPB / 32; i++) tot += wred[i];
        out[b] = tot + head_b[0];
    }
}

extern "C" void kernel_launch(void* const* d_in, const int* in_sizes, int n_in,
                              void* d_out, int out_size) {
    const float* x      = (const float*)d_in[0];
    const float* params = (const float*)d_in[1];
    const float* head_w = (const float*)d_in[2];
    const float* head_b = (const float*)d_in[3];
    float* out = (float*)d_out;
    int B = in_sizes[0] / NQ;
    prep_gates<<<1, 64>>>(params);
    qsim<<<B, TPB>>>(x, head_w, head_b, out);
}